// round 5
// baseline (speedup 1.0000x reference)
#include <cuda_runtime.h>
#include <cuda_bf16.h>
#include <cstdint>

#define HH 512
#define WW 512
#define BATCH 32
#define THREADS 128
#define OUTW 256          // output cols per tile (2 per thread)
#define OUTH 32           // output rows per tile
#define SPITCH 264        // smem row pitch (floats): 4 left halo + 256 + 4 right
#define TILE_H (OUTH + 6) // 38
#define NCH 66            // 16-byte chunks per row per map (264 floats / 4)

typedef unsigned long long u64;

__device__ double g_acc = 0.0;
__device__ unsigned int g_tick = 0;

// ---- packed f32x2 helpers ----
static __device__ __forceinline__ u64 fma2_(u64 a, u64 b, u64 c) {
    u64 d; asm("fma.rn.f32x2 %0,%1,%2,%3;" : "=l"(d) : "l"(a), "l"(b), "l"(c)); return d;
}
static __device__ __forceinline__ u64 mul2_(u64 a, u64 b) {
    u64 d; asm("mul.rn.f32x2 %0,%1,%2;" : "=l"(d) : "l"(a), "l"(b)); return d;
}
static __device__ __forceinline__ u64 add2_(u64 a, u64 b) {
    u64 d; asm("add.rn.f32x2 %0,%1,%2;" : "=l"(d) : "l"(a), "l"(b)); return d;
}
static __device__ __forceinline__ u64 pk2(float lo, float hi) {
    u64 r; asm("mov.b64 %0,{%1,%2};" : "=l"(r) : "f"(lo), "f"(hi)); return r;
}
static __device__ __forceinline__ void upk2(u64 v, float& lo, float& hi) {
    asm("mov.b64 {%0,%1},%2;" : "=f"(lo), "=f"(hi) : "l"(v));
}
static __device__ __forceinline__ u64 neg2_(u64 a) { return a ^ 0x8000000080000000ULL; }
static __device__ __forceinline__ u64 sh2_(u64 a, u64 b) { return (a >> 32) | (b << 32); }

static __device__ __forceinline__ void cp16(unsigned saddr, const float* gaddr, int srcsz) {
    asm volatile("cp.async.ca.shared.global [%0], [%1], 16, %2;"
                 :: "r"(saddr), "l"(gaddr), "r"(srcsz));
}

__global__ __launch_bounds__(THREADS) void ssim_main(const float* __restrict__ x,
                                                     const float* __restrict__ y,
                                                     const float* __restrict__ kern,
                                                     float* __restrict__ out,
                                                     int nblocks)
{
    extern __shared__ float smem_dyn[];
    float (*sx)[SPITCH] = (float (*)[SPITCH])smem_dyn;
    float (*sy)[SPITCH] = (float (*)[SPITCH])(smem_dyn + TILE_H * SPITCH);
    __shared__ float wsum[4];

    const int tid  = threadIdx.x;
    const int col0 = blockIdx.x * OUTW;
    const int row0 = blockIdx.y * OUTH;
    const long base = (long)blockIdx.z * (HH * WW);

    // separable 1-D weights: v_i = sqrt(k[i][i])
    u64 w2[7];
#pragma unroll
    for (int t = 0; t < 7; t++) {
        float wt = sqrtf(__ldg(kern + t * 7 + t));
        w2[t] = pk2(wt, wt);
    }

    // ---- stage x,y tile via cp.async 16B chunks (zfill out-of-range) ----
    // smem col s <-> global col (col0 - 4 + s); row r <-> global row (row0 - 3 + r).
    // Chunks are 4-float aligned in both smem and gmem; since col0 in {0,256},
    // every chunk is fully in-image or fully out (clean zfill, no partials).
    for (int i = tid; i < TILE_H * 2 * NCH; i += THREADS) {
        int r   = i / (2 * NCH);
        int rem = i - r * (2 * NCH);
        int m   = rem / NCH;
        int j   = rem - m * NCH;
        int gr  = row0 - 3 + r;
        int gc  = col0 - 4 + 4 * j;
        bool ok = (gr >= 0) && (gr < HH) && (gc >= 0) && (gc < WW);
        const float* gp = (m ? y : x);
        const float* src = ok ? (gp + base + (long)gr * WW + gc) : gp;
        float* dst = (m ? sy[r] : sx[r]) + 4 * j;
        cp16((unsigned)__cvta_generic_to_shared(dst), src, ok ? 16 : 0);
    }
    asm volatile("cp.async.commit_group;");
    asm volatile("cp.async.wait_group 0;");
    __syncthreads();

    const u64 two2 = pk2(2.f, 2.f);
    const u64 c1_2 = pk2(1e-4f, 1e-4f);
    const u64 c2_2 = pk2(9e-4f, 9e-4f);

    u64 Wx[7], Wy[7], Wxx[7], Wyy[7], Wxy[7];
    float sum = 0.f;

    // horizontal 7-tap conv of (x,y,xx,yy,xy); outputs packed pair for global
    // cols (col0+2tid, col0+2tid+1). Aligned LDS.64 at smem cols 2tid..2tid+9;
    // tap t (lo pixel) lives at smem col 2tid+1+t.
#define HCONV(r, s)                                                          \
    {                                                                        \
        const float* rx_ = &sx[(r)][2 * tid];                                \
        const float* ry_ = &sy[(r)][2 * tid];                                \
        u64 e0 = *(const u64*)(rx_ + 0), e1 = *(const u64*)(rx_ + 2);        \
        u64 e2 = *(const u64*)(rx_ + 4), e3 = *(const u64*)(rx_ + 6);        \
        u64 e4 = *(const u64*)(rx_ + 8);                                     \
        u64 f0 = *(const u64*)(ry_ + 0), f1 = *(const u64*)(ry_ + 2);        \
        u64 f2 = *(const u64*)(ry_ + 4), f3 = *(const u64*)(ry_ + 6);        \
        u64 f4 = *(const u64*)(ry_ + 8);                                     \
        u64 xp[7] = {sh2_(e0, e1), e1, sh2_(e1, e2), e2,                     \
                     sh2_(e2, e3), e3, sh2_(e3, e4)};                        \
        u64 yp[7] = {sh2_(f0, f1), f1, sh2_(f1, f2), f2,                     \
                     sh2_(f2, f3), f3, sh2_(f3, f4)};                        \
        u64 wx0 = mul2_(w2[0], xp[0]);                                       \
        u64 wy0 = mul2_(w2[0], yp[0]);                                       \
        u64 a_ = wx0, b_ = wy0;                                              \
        u64 cxx_ = mul2_(wx0, xp[0]);                                        \
        u64 cyy_ = mul2_(wy0, yp[0]);                                        \
        u64 cxy_ = mul2_(wx0, yp[0]);                                        \
        _Pragma("unroll")                                                    \
        for (int t = 1; t < 7; t++) {                                        \
            u64 wx = mul2_(w2[t], xp[t]);                                    \
            u64 wy = mul2_(w2[t], yp[t]);                                    \
            a_   = add2_(a_, wx);                                            \
            b_   = add2_(b_, wy);                                            \
            cxx_ = fma2_(wx, xp[t], cxx_);                                   \
            cyy_ = fma2_(wy, yp[t], cyy_);                                   \
            cxy_ = fma2_(wx, yp[t], cxy_);                                   \
        }                                                                    \
        Wx[(s)] = a_; Wy[(s)] = b_;                                          \
        Wxx[(s)] = cxx_; Wyy[(s)] = cyy_; Wxy[(s)] = cxy_;                   \
    }

#pragma unroll
    for (int r = 0; r < 6; r++) {
        HCONV(r, r);
    }

#pragma unroll
    for (int r = 6; r < TILE_H; r++) {
        HCONV(r, r % 7);

        u64 mx  = mul2_(w2[0], Wx[(r - 6) % 7]);
        u64 my  = mul2_(w2[0], Wy[(r - 6) % 7]);
        u64 exx = mul2_(w2[0], Wxx[(r - 6) % 7]);
        u64 eyy = mul2_(w2[0], Wyy[(r - 6) % 7]);
        u64 exy = mul2_(w2[0], Wxy[(r - 6) % 7]);
#pragma unroll
        for (int t = 1; t < 7; t++) {
            int s = (r - 6 + t) % 7;
            mx  = fma2_(w2[t], Wx[s],  mx);
            my  = fma2_(w2[t], Wy[s],  my);
            exx = fma2_(w2[t], Wxx[s], exx);
            eyy = fma2_(w2[t], Wyy[s], eyy);
            exy = fma2_(w2[t], Wxy[s], exy);
        }

        u64 nmx = neg2_(mx);
        u64 sxx = fma2_(nmx, mx, exx);
        u64 syy = fma2_(neg2_(my), my, eyy);
        u64 sxy = fma2_(nmx, my, exy);

        u64 mxmy = mul2_(mx, my);
        u64 n1 = fma2_(two2, mxmy, c1_2);
        u64 n2 = fma2_(two2, sxy, c2_2);
        u64 num = mul2_(n1, n2);

        u64 myy = mul2_(my, my);
        u64 d1 = fma2_(mx, mx, myy);
        d1 = add2_(d1, c1_2);
        u64 d2 = add2_(add2_(sxx, syy), c2_2);
        u64 den = mul2_(d1, d2);

        float nlo, nhi, dlo, dhi;
        upk2(num, nlo, nhi);
        upk2(den, dlo, dhi);
        sum += __fdividef(nlo, dlo) + __fdividef(nhi, dhi);
    }
#undef HCONV

    // ---- block reduction ----
#pragma unroll
    for (int off = 16; off; off >>= 1)
        sum += __shfl_down_sync(0xffffffffu, sum, off);
    if ((tid & 31) == 0) wsum[tid >> 5] = sum;
    __syncthreads();

    // ---- last-block finalize (single-kernel) ----
    if (tid == 0) {
        float s = wsum[0] + wsum[1] + wsum[2] + wsum[3];
        atomicAdd(&g_acc, (double)s);
        __threadfence();
        unsigned t = atomicAdd(&g_tick, 1u);
        if (t == (unsigned)(nblocks - 1)) {
            double v = *(volatile double*)&g_acc;
            out[0] = (float)(v / ((double)BATCH * HH * WW));
            g_acc = 0.0;          // reset for next graph replay
            g_tick = 0;
            __threadfence();
        }
    }
}

extern "C" void kernel_launch(void* const* d_in, const int* in_sizes, int n_in,
                              void* d_out, int out_size)
{
    const float* x = (const float*)d_in[0];
    const float* y = (const float*)d_in[1];
    const float* k = (const float*)d_in[2];
    float* out = (float*)d_out;

    static int configured = 0;
    const int smem_bytes = 2 * TILE_H * SPITCH * (int)sizeof(float);
    if (!configured) {
        cudaFuncSetAttribute(ssim_main, cudaFuncAttributeMaxDynamicSharedMemorySize,
                             smem_bytes);
        configured = 1;
    }

    dim3 grid(WW / OUTW, HH / OUTH, BATCH);
    int nblocks = grid.x * grid.y * grid.z;
    ssim_main<<<grid, THREADS, smem_bytes>>>(x, y, k, out, nblocks);
}

// round 6
// speedup vs baseline: 1.2665x; 1.2665x over previous
#include <cuda_runtime.h>
#include <cuda_bf16.h>
#include <cstdint>

#define HH 512
#define WW 512
#define BATCH 32
#define THREADS 128
#define OUTW 256          // output cols per tile (2 per thread)
#define OUTH 16           // output rows per tile
#define SPITCH 264        // smem row pitch (floats): 4 left halo + 256 + 4 right
#define TILE_H (OUTH + 6) // 22
#define NCH 66            // 16-byte chunks per row per map (264 floats / 4)

typedef unsigned long long u64;

__device__ double g_acc = 0.0;
__device__ unsigned int g_tick = 0;

// ---- packed f32x2 helpers ----
static __device__ __forceinline__ u64 fma2_(u64 a, u64 b, u64 c) {
    u64 d; asm("fma.rn.f32x2 %0,%1,%2,%3;" : "=l"(d) : "l"(a), "l"(b), "l"(c)); return d;
}
static __device__ __forceinline__ u64 mul2_(u64 a, u64 b) {
    u64 d; asm("mul.rn.f32x2 %0,%1,%2;" : "=l"(d) : "l"(a), "l"(b)); return d;
}
static __device__ __forceinline__ u64 add2_(u64 a, u64 b) {
    u64 d; asm("add.rn.f32x2 %0,%1,%2;" : "=l"(d) : "l"(a), "l"(b)); return d;
}
static __device__ __forceinline__ u64 pk2(float lo, float hi) {
    u64 r; asm("mov.b64 %0,{%1,%2};" : "=l"(r) : "f"(lo), "f"(hi)); return r;
}
static __device__ __forceinline__ void upk2(u64 v, float& lo, float& hi) {
    asm("mov.b64 {%0,%1},%2;" : "=f"(lo), "=f"(hi) : "l"(v));
}
static __device__ __forceinline__ u64 neg2_(u64 a) { return a ^ 0x8000000080000000ULL; }
// pair {hi(a), lo(b)} — register re-pairing only (no shifts)
static __device__ __forceinline__ u64 sh2_(u64 a, u64 b) {
    unsigned al, ah, bl, bh;
    asm("mov.b64 {%0,%1},%2;" : "=r"(al), "=r"(ah) : "l"(a));
    asm("mov.b64 {%0,%1},%2;" : "=r"(bl), "=r"(bh) : "l"(b));
    u64 r;
    asm("mov.b64 %0,{%1,%2};" : "=l"(r) : "r"(ah), "r"(bl));
    return r;
}

static __device__ __forceinline__ void cp16(unsigned saddr, const float* gaddr, int srcsz) {
    asm volatile("cp.async.cg.shared.global [%0], [%1], 16, %2;"
                 :: "r"(saddr), "l"(gaddr), "r"(srcsz));
}

__global__ __launch_bounds__(THREADS) void ssim_main(const float* __restrict__ x,
                                                     const float* __restrict__ y,
                                                     const float* __restrict__ kern,
                                                     float* __restrict__ out,
                                                     int nblocks)
{
    extern __shared__ float smem_dyn[];
    float (*sx)[SPITCH] = (float (*)[SPITCH])smem_dyn;
    float (*sy)[SPITCH] = (float (*)[SPITCH])(smem_dyn + TILE_H * SPITCH);
    __shared__ float wsum[4];

    const int tid  = threadIdx.x;
    const int col0 = blockIdx.x * OUTW;
    const int row0 = blockIdx.y * OUTH;
    const long base = (long)blockIdx.z * (HH * WW);

    // separable 1-D weights: v_i = sqrt(k[i][i])
    u64 w2[7];
#pragma unroll
    for (int t = 0; t < 7; t++) {
        float wt = sqrtf(__ldg(kern + t * 7 + t));
        w2[t] = pk2(wt, wt);
    }

    // ---- stage x,y tile via cp.async 16B chunks (zfill out-of-range) ----
    // smem col s <-> global col (col0 - 4 + s); row r <-> global row (row0 - 3 + r).
    // Each item = one (row, chunk) position; thread copies BOTH x and y chunks.
    // Since col0 in {0,256}, each chunk is fully in-image or fully out (clean zfill).
    for (int i = tid; i < TILE_H * NCH; i += THREADS) {
        int r  = i / NCH;
        int j  = i - r * NCH;
        int gr = row0 - 3 + r;
        int gc = col0 - 4 + 4 * j;
        bool ok = (gr >= 0) && (gr < HH) && (gc >= 0) && (gc < WW);
        long gi = base + (long)gr * WW + gc;
        const float* srcx = ok ? (x + gi) : x;
        const float* srcy = ok ? (y + gi) : y;
        int sz = ok ? 16 : 0;
        cp16((unsigned)__cvta_generic_to_shared(sx[r] + 4 * j), srcx, sz);
        cp16((unsigned)__cvta_generic_to_shared(sy[r] + 4 * j), srcy, sz);
    }
    asm volatile("cp.async.commit_group;");
    asm volatile("cp.async.wait_group 0;");
    __syncthreads();

    const u64 two2 = pk2(2.f, 2.f);
    const u64 c1_2 = pk2(1e-4f, 1e-4f);
    const u64 c2_2 = pk2(9e-4f, 9e-4f);

    u64 Wx[7], Wy[7], Wxx[7], Wyy[7], Wxy[7];
    float sum = 0.f;

    // horizontal 7-tap conv of (x,y,xx,yy,xy); outputs packed pair for global
    // cols (col0+2tid, col0+2tid+1). Aligned LDS.64 at smem cols 2tid..2tid+9;
    // tap t (lo pixel) lives at smem col 2tid+1+t.
#define HCONV(r, s)                                                          \
    {                                                                        \
        const float* rx_ = &sx[(r)][2 * tid];                                \
        const float* ry_ = &sy[(r)][2 * tid];                                \
        u64 e0 = *(const u64*)(rx_ + 0), e1 = *(const u64*)(rx_ + 2);        \
        u64 e2 = *(const u64*)(rx_ + 4), e3 = *(const u64*)(rx_ + 6);        \
        u64 e4 = *(const u64*)(rx_ + 8);                                     \
        u64 f0 = *(const u64*)(ry_ + 0), f1 = *(const u64*)(ry_ + 2);        \
        u64 f2 = *(const u64*)(ry_ + 4), f3 = *(const u64*)(ry_ + 6);        \
        u64 f4 = *(const u64*)(ry_ + 8);                                     \
        u64 xp[7] = {sh2_(e0, e1), e1, sh2_(e1, e2), e2,                     \
                     sh2_(e2, e3), e3, sh2_(e3, e4)};                        \
        u64 yp[7] = {sh2_(f0, f1), f1, sh2_(f1, f2), f2,                     \
                     sh2_(f2, f3), f3, sh2_(f3, f4)};                        \
        u64 wx0 = mul2_(w2[0], xp[0]);                                       \
        u64 wy0 = mul2_(w2[0], yp[0]);                                       \
        u64 a_ = wx0, b_ = wy0;                                              \
        u64 cxx_ = mul2_(wx0, xp[0]);                                        \
        u64 cyy_ = mul2_(wy0, yp[0]);                                        \
        u64 cxy_ = mul2_(wx0, yp[0]);                                        \
        _Pragma("unroll")                                                    \
        for (int t = 1; t < 7; t++) {                                        \
            u64 wx = mul2_(w2[t], xp[t]);                                    \
            u64 wy = mul2_(w2[t], yp[t]);                                    \
            a_   = add2_(a_, wx);                                            \
            b_   = add2_(b_, wy);                                            \
            cxx_ = fma2_(wx, xp[t], cxx_);                                   \
            cyy_ = fma2_(wy, yp[t], cyy_);                                   \
            cxy_ = fma2_(wx, yp[t], cxy_);                                   \
        }                                                                    \
        Wx[(s)] = a_; Wy[(s)] = b_;                                          \
        Wxx[(s)] = cxx_; Wyy[(s)] = cyy_; Wxy[(s)] = cxy_;                   \
    }

#pragma unroll
    for (int r = 0; r < 6; r++) {
        HCONV(r, r);
    }

#pragma unroll
    for (int r = 6; r < TILE_H; r++) {
        HCONV(r, r % 7);

        u64 mx  = mul2_(w2[0], Wx[(r - 6) % 7]);
        u64 my  = mul2_(w2[0], Wy[(r - 6) % 7]);
        u64 exx = mul2_(w2[0], Wxx[(r - 6) % 7]);
        u64 eyy = mul2_(w2[0], Wyy[(r - 6) % 7]);
        u64 exy = mul2_(w2[0], Wxy[(r - 6) % 7]);
#pragma unroll
        for (int t = 1; t < 7; t++) {
            int s = (r - 6 + t) % 7;
            mx  = fma2_(w2[t], Wx[s],  mx);
            my  = fma2_(w2[t], Wy[s],  my);
            exx = fma2_(w2[t], Wxx[s], exx);
            eyy = fma2_(w2[t], Wyy[s], eyy);
            exy = fma2_(w2[t], Wxy[s], exy);
        }

        u64 nmx = neg2_(mx);
        u64 sxx = fma2_(nmx, mx, exx);
        u64 syy = fma2_(neg2_(my), my, eyy);
        u64 sxy = fma2_(nmx, my, exy);

        u64 mxmy = mul2_(mx, my);
        u64 n1 = fma2_(two2, mxmy, c1_2);
        u64 n2 = fma2_(two2, sxy, c2_2);
        u64 num = mul2_(n1, n2);

        u64 myy = mul2_(my, my);
        u64 d1 = fma2_(mx, mx, myy);
        d1 = add2_(d1, c1_2);
        u64 d2 = add2_(add2_(sxx, syy), c2_2);
        u64 den = mul2_(d1, d2);

        float nlo, nhi, dlo, dhi;
        upk2(num, nlo, nhi);
        upk2(den, dlo, dhi);
        sum += __fdividef(nlo, dlo) + __fdividef(nhi, dhi);
    }
#undef HCONV

    // ---- block reduction ----
#pragma unroll
    for (int off = 16; off; off >>= 1)
        sum += __shfl_down_sync(0xffffffffu, sum, off);
    if ((tid & 31) == 0) wsum[tid >> 5] = sum;
    __syncthreads();

    // ---- last-block finalize (single-kernel) ----
    if (tid == 0) {
        float s = wsum[0] + wsum[1] + wsum[2] + wsum[3];
        atomicAdd(&g_acc, (double)s);
        __threadfence();
        unsigned t = atomicAdd(&g_tick, 1u);
        if (t == (unsigned)(nblocks - 1)) {
            double v = *(volatile double*)&g_acc;
            out[0] = (float)(v / ((double)BATCH * HH * WW));
            g_acc = 0.0;          // reset for next graph replay
            g_tick = 0;
            __threadfence();
        }
    }
}

extern "C" void kernel_launch(void* const* d_in, const int* in_sizes, int n_in,
                              void* d_out, int out_size)
{
    const float* x = (const float*)d_in[0];
    const float* y = (const float*)d_in[1];
    const float* k = (const float*)d_in[2];
    float* out = (float*)d_out;

    static int configured = 0;
    const int smem_bytes = 2 * TILE_H * SPITCH * (int)sizeof(float);
    if (!configured) {
        cudaFuncSetAttribute(ssim_main, cudaFuncAttributeMaxDynamicSharedMemorySize,
                             smem_bytes);
        configured = 1;
    }

    dim3 grid(WW / OUTW, HH / OUTH, BATCH);
    int nblocks = grid.x * grid.y * grid.z;
    ssim_main<<<grid, THREADS, smem_bytes>>>(x, y, k, out, nblocks);
}

// round 7
// speedup vs baseline: 1.2753x; 1.0070x over previous
#include <cuda_runtime.h>
#include <cuda_bf16.h>
#include <cstdint>

#define HH 512
#define WW 512
#define BATCH 32
#define THREADS 128
#define OUTW 256          // output cols per tile (2 per thread)
#define OUTH 16           // output rows per tile
#define SPITCH 264        // smem row pitch (floats): 4 left halo + 256 + 4 right
#define TILE_H (OUTH + 6) // 22
#define NCH 66            // 16-byte chunks per row per map (264 floats / 4)

typedef unsigned long long u64;

__device__ double g_acc = 0.0;
__device__ unsigned int g_tick = 0;

// ---- packed f32x2 helpers ----
static __device__ __forceinline__ u64 fma2_(u64 a, u64 b, u64 c) {
    u64 d; asm("fma.rn.f32x2 %0,%1,%2,%3;" : "=l"(d) : "l"(a), "l"(b), "l"(c)); return d;
}
static __device__ __forceinline__ u64 mul2_(u64 a, u64 b) {
    u64 d; asm("mul.rn.f32x2 %0,%1,%2;" : "=l"(d) : "l"(a), "l"(b)); return d;
}
static __device__ __forceinline__ u64 add2_(u64 a, u64 b) {
    u64 d; asm("add.rn.f32x2 %0,%1,%2;" : "=l"(d) : "l"(a), "l"(b)); return d;
}
static __device__ __forceinline__ u64 pk2(float lo, float hi) {
    u64 r; asm("mov.b64 %0,{%1,%2};" : "=l"(r) : "f"(lo), "f"(hi)); return r;
}
static __device__ __forceinline__ void upk2(u64 v, float& lo, float& hi) {
    asm("mov.b64 {%0,%1},%2;" : "=f"(lo), "=f"(hi) : "l"(v));
}
static __device__ __forceinline__ u64 neg2_(u64 a) { return a ^ 0x8000000080000000ULL; }
// pair {hi(a), lo(b)} — register re-pairing only (no shifts)
static __device__ __forceinline__ u64 sh2_(u64 a, u64 b) {
    unsigned al, ah, bl, bh;
    asm("mov.b64 {%0,%1},%2;" : "=r"(al), "=r"(ah) : "l"(a));
    asm("mov.b64 {%0,%1},%2;" : "=r"(bl), "=r"(bh) : "l"(b));
    u64 r;
    asm("mov.b64 %0,{%1,%2};" : "=l"(r) : "r"(ah), "r"(bl));
    return r;
}

static __device__ __forceinline__ void cp16(unsigned saddr, const float* gaddr, int srcsz) {
    asm volatile("cp.async.cg.shared.global [%0], [%1], 16, %2;"
                 :: "r"(saddr), "l"(gaddr), "r"(srcsz));
}

__global__ __launch_bounds__(THREADS) void ssim_main(const float* __restrict__ x,
                                                     const float* __restrict__ y,
                                                     const float* __restrict__ kern,
                                                     float* __restrict__ out,
                                                     int nblocks)
{
    extern __shared__ float smem_dyn[];
    float (*sx)[SPITCH] = (float (*)[SPITCH])smem_dyn;
    float (*sy)[SPITCH] = (float (*)[SPITCH])(smem_dyn + TILE_H * SPITCH);
    __shared__ float wsum[4];

    const int tid  = threadIdx.x;
    const int col0 = blockIdx.x * OUTW;
    const int row0 = blockIdx.y * OUTH;
    const long base = (long)blockIdx.z * (HH * WW);

    // separable 1-D weights: v_i = sqrt(k[i][i])
    u64 w2[7];
#pragma unroll
    for (int t = 0; t < 7; t++) {
        float wt = sqrtf(__ldg(kern + t * 7 + t));
        w2[t] = pk2(wt, wt);
    }

    // ---- stage x,y tile via cp.async 16B chunks (zfill out-of-range) ----
    // smem col s <-> global col (col0 - 4 + s); row r <-> global row (row0 - 3 + r).
    // Each item = one (row, chunk) position; thread copies BOTH x and y chunks.
    // Since col0 in {0,256}, each chunk is fully in-image or fully out (clean zfill).
    for (int i = tid; i < TILE_H * NCH; i += THREADS) {
        int r  = i / NCH;
        int j  = i - r * NCH;
        int gr = row0 - 3 + r;
        int gc = col0 - 4 + 4 * j;
        bool ok = (gr >= 0) && (gr < HH) && (gc >= 0) && (gc < WW);
        long gi = base + (long)gr * WW + gc;
        const float* srcx = ok ? (x + gi) : x;
        const float* srcy = ok ? (y + gi) : y;
        int sz = ok ? 16 : 0;
        cp16((unsigned)__cvta_generic_to_shared(sx[r] + 4 * j), srcx, sz);
        cp16((unsigned)__cvta_generic_to_shared(sy[r] + 4 * j), srcy, sz);
    }
    asm volatile("cp.async.commit_group;");
    asm volatile("cp.async.wait_group 0;");
    __syncthreads();

    const u64 two2 = pk2(2.f, 2.f);
    const u64 c1_2 = pk2(1e-4f, 1e-4f);
    const u64 c2_2 = pk2(9e-4f, 9e-4f);

    u64 Wx[7], Wy[7], Wxx[7], Wyy[7], Wxy[7];
    float sum = 0.f;

    // horizontal 7-tap conv of (x,y,xx,yy,xy); outputs packed pair for global
    // cols (col0+2tid, col0+2tid+1). Aligned LDS.64 at smem cols 2tid..2tid+9;
    // tap t (lo pixel) lives at smem col 2tid+1+t.
#define HCONV(r, s)                                                          \
    {                                                                        \
        const float* rx_ = &sx[(r)][2 * tid];                                \
        const float* ry_ = &sy[(r)][2 * tid];                                \
        u64 e0 = *(const u64*)(rx_ + 0), e1 = *(const u64*)(rx_ + 2);        \
        u64 e2 = *(const u64*)(rx_ + 4), e3 = *(const u64*)(rx_ + 6);        \
        u64 e4 = *(const u64*)(rx_ + 8);                                     \
        u64 f0 = *(const u64*)(ry_ + 0), f1 = *(const u64*)(ry_ + 2);        \
        u64 f2 = *(const u64*)(ry_ + 4), f3 = *(const u64*)(ry_ + 6);        \
        u64 f4 = *(const u64*)(ry_ + 8);                                     \
        u64 xp[7] = {sh2_(e0, e1), e1, sh2_(e1, e2), e2,                     \
                     sh2_(e2, e3), e3, sh2_(e3, e4)};                        \
        u64 yp[7] = {sh2_(f0, f1), f1, sh2_(f1, f2), f2,                     \
                     sh2_(f2, f3), f3, sh2_(f3, f4)};                        \
        u64 wx0 = mul2_(w2[0], xp[0]);                                       \
        u64 wy0 = mul2_(w2[0], yp[0]);                                       \
        u64 a_ = wx0, b_ = wy0;                                              \
        u64 cxx_ = mul2_(wx0, xp[0]);                                        \
        u64 cyy_ = mul2_(wy0, yp[0]);                                        \
        u64 cxy_ = mul2_(wx0, yp[0]);                                        \
        _Pragma("unroll")                                                    \
        for (int t = 1; t < 7; t++) {                                        \
            u64 wx = mul2_(w2[t], xp[t]);                                    \
            u64 wy = mul2_(w2[t], yp[t]);                                    \
            a_   = add2_(a_, wx);                                            \
            b_   = add2_(b_, wy);                                            \
            cxx_ = fma2_(wx, xp[t], cxx_);                                   \
            cyy_ = fma2_(wy, yp[t], cyy_);                                   \
            cxy_ = fma2_(wx, yp[t], cxy_);                                   \
        }                                                                    \
        Wx[(s)] = a_; Wy[(s)] = b_;                                          \
        Wxx[(s)] = cxx_; Wyy[(s)] = cyy_; Wxy[(s)] = cxy_;                   \
    }

#pragma unroll
    for (int r = 0; r < 6; r++) {
        HCONV(r, r);
    }

#pragma unroll
    for (int r = 6; r < TILE_H; r++) {
        HCONV(r, r % 7);

        u64 mx  = mul2_(w2[0], Wx[(r - 6) % 7]);
        u64 my  = mul2_(w2[0], Wy[(r - 6) % 7]);
        u64 exx = mul2_(w2[0], Wxx[(r - 6) % 7]);
        u64 eyy = mul2_(w2[0], Wyy[(r - 6) % 7]);
        u64 exy = mul2_(w2[0], Wxy[(r - 6) % 7]);
#pragma unroll
        for (int t = 1; t < 7; t++) {
            int s = (r - 6 + t) % 7;
            mx  = fma2_(w2[t], Wx[s],  mx);
            my  = fma2_(w2[t], Wy[s],  my);
            exx = fma2_(w2[t], Wxx[s], exx);
            eyy = fma2_(w2[t], Wyy[s], eyy);
            exy = fma2_(w2[t], Wxy[s], exy);
        }

        u64 nmx = neg2_(mx);
        u64 sxx = fma2_(nmx, mx, exx);
        u64 syy = fma2_(neg2_(my), my, eyy);
        u64 sxy = fma2_(nmx, my, exy);

        u64 mxmy = mul2_(mx, my);
        u64 n1 = fma2_(two2, mxmy, c1_2);
        u64 n2 = fma2_(two2, sxy, c2_2);
        u64 num = mul2_(n1, n2);

        u64 myy = mul2_(my, my);
        u64 d1 = fma2_(mx, mx, myy);
        d1 = add2_(d1, c1_2);
        u64 d2 = add2_(add2_(sxx, syy), c2_2);
        u64 den = mul2_(d1, d2);

        float nlo, nhi, dlo, dhi;
        upk2(num, nlo, nhi);
        upk2(den, dlo, dhi);
        sum += __fdividef(nlo, dlo) + __fdividef(nhi, dhi);
    }
#undef HCONV

    // ---- block reduction ----
#pragma unroll
    for (int off = 16; off; off >>= 1)
        sum += __shfl_down_sync(0xffffffffu, sum, off);
    if ((tid & 31) == 0) wsum[tid >> 5] = sum;
    __syncthreads();

    // ---- last-block finalize (single-kernel) ----
    if (tid == 0) {
        float s = wsum[0] + wsum[1] + wsum[2] + wsum[3];
        atomicAdd(&g_acc, (double)s);
        __threadfence();
        unsigned t = atomicAdd(&g_tick, 1u);
        if (t == (unsigned)(nblocks - 1)) {
            double v = *(volatile double*)&g_acc;
            out[0] = (float)(v / ((double)BATCH * HH * WW));
            g_acc = 0.0;          // reset for next graph replay
            g_tick = 0;
            __threadfence();
        }
    }
}

extern "C" void kernel_launch(void* const* d_in, const int* in_sizes, int n_in,
                              void* d_out, int out_size)
{
    const float* x = (const float*)d_in[0];
    const float* y = (const float*)d_in[1];
    const float* k = (const float*)d_in[2];
    float* out = (float*)d_out;

    static int configured = 0;
    const int smem_bytes = 2 * TILE_H * SPITCH * (int)sizeof(float);
    if (!configured) {
        cudaFuncSetAttribute(ssim_main, cudaFuncAttributeMaxDynamicSharedMemorySize,
                             smem_bytes);
        configured = 1;
    }

    dim3 grid(WW / OUTW, HH / OUTH, BATCH);
    int nblocks = grid.x * grid.y * grid.z;
    ssim_main<<<grid, THREADS, smem_bytes>>>(x, y, k, out, nblocks);
}